// round 16
// baseline (speedup 1.0000x reference)
#include <cuda_runtime.h>
#include <cuda_fp16.h>
#include <cstdint>

#define S_LEN 4096
#define HID   2048
#define NH    16
#define NKV   4
#define HD    128
#define NBLK  32
#define QKV_N 3072          // NH*HD + 2*NKV*HD
#define NEGV  -1000000000.0f
// HD^-0.5 * log2(e): softmax runs in the exp2 domain
#define QSCALE (0.08838834764831845f * 1.4426950408889634f)

// ---------------- scratch (half operands) ----------------
__device__ __half g_Hh[S_LEN * HID];
__device__ __half g_QKVh[(size_t)S_LEN * QKV_N];          // Q | K | V column slices
__device__ __half g_VTh[(size_t)NKV * HD * S_LEN];
__device__ __half g_Oh[S_LEN * NH * HD];
__device__ __half g_WqkvT[(size_t)QKV_N * HID];           // [WqT;WkT;WvT] rows
__device__ __half g_WoTh[(size_t)NH * HD * HID];

// ---------------- helpers ----------------
__device__ __forceinline__ uint32_t smem_u32(const void* p) {
    uint32_t a;
    asm("{ .reg .u64 t; cvta.to.shared.u64 t, %1; cvt.u32.u64 %0, t; }" : "=r"(a) : "l"(p));
    return a;
}
__device__ __forceinline__ float ex2f(float x) {
    float y;
    asm("ex2.approx.ftz.f32 %0, %1;" : "=f"(y) : "f"(x));
    return y;
}
__device__ __forceinline__ uint32_t packh2(float x, float y) {
    __half2 h = __floats2half2_rn(x, y);
    return *(uint32_t*)&h;
}
__device__ __forceinline__ void cp16(uint32_t dst, const void* src) {
    asm volatile("cp.async.cg.shared.global [%0], [%1], 16;" :: "r"(dst), "l"(src));
}
#define CP_COMMIT() asm volatile("cp.async.commit_group;" ::: "memory")
#define CP_WAIT0()  asm volatile("cp.async.wait_group 0;" ::: "memory")
#define CP_WAIT1()  asm volatile("cp.async.wait_group 1;" ::: "memory")
#define CP_WAIT2()  asm volatile("cp.async.wait_group 2;" ::: "memory")

__device__ __forceinline__ void mma_f16(float c[4], const uint32_t a[4],
                                        uint32_t b0, uint32_t b1) {
    asm volatile(
        "mma.sync.aligned.m16n8k16.row.col.f32.f16.f16.f32 "
        "{%0,%1,%2,%3}, {%4,%5,%6,%7}, {%8,%9}, {%0,%1,%2,%3};"
        : "+f"(c[0]), "+f"(c[1]), "+f"(c[2]), "+f"(c[3])
        : "r"(a[0]), "r"(a[1]), "r"(a[2]), "r"(a[3]), "r"(b0), "r"(b1));
}
__device__ __forceinline__ void ldm_x4(uint32_t r[4], uint32_t addr) {
    asm volatile("ldmatrix.sync.aligned.m8n8.x4.shared.b16 {%0,%1,%2,%3}, [%4];"
                 : "=r"(r[0]), "=r"(r[1]), "=r"(r[2]), "=r"(r[3]) : "r"(addr));
}

// ---------------- key-block schedule ----------------
__device__ __forceinline__ int key_block(int n, int j, bool* valid) {
    if (j < 4) {
        int kb = n - 3 + j;
        *valid = (kb >= 0);
        return kb < 0 ? 0 : kb;
    }
    int jj = j - 4;
    if (jj == 0) { *valid = true; return 0; }
    int off = (4 - jj) * 8;
    int kb = n - off; if (kb < 0) kb = 0;
    int kprev;
    if (jj == 1) kprev = 0;
    else { int po = (5 - jj) * 8; kprev = n - po; if (kprev < 0) kprev = 0; }
    *valid = (kb != kprev);
    return kb;
}

// ---------------- smem tile: 128 rows x 64 halfs (128B), XOR swizzled -----
__device__ __forceinline__ void fill_tile(uint32_t st, const __half* src, int stride, int tid) {
#pragma unroll
    for (int i = 0; i < 4; i++) {
        int idx = tid + i * 256;
        int r = idx >> 3, c8 = idx & 7;
        cp16(st + (uint32_t)((r << 3) + (c8 ^ (r & 7))) * 16,
             src + (size_t)r * stride + c8 * 8);
    }
}

// ---------------- fp16 128x256x64 compute, 64x64 warp tiles (GEMM) --------
// B tile is 256 rows x 64 halfs = two consecutive 16KB sub-tiles; the
// swizzle address r*128 + ((kc^(r&7))<<4) extends unchanged to r<256.
__device__ __forceinline__ void compute_tile_w64(uint32_t aB, uint32_t bB,
                                                 float acc[4][8][4],
                                                 int lane, int wm, int wn) {
    int g = lane >> 3, l7 = lane & 7;
    int aRow = ((g & 1) << 3) + l7, aKc = g >> 1;
    int bRow = ((g >> 1) << 3) + l7, bKc = g & 1;
#pragma unroll
    for (int ks = 0; ks < 4; ks++) {
        uint32_t a[4][4], b[4][4];
#pragma unroll
        for (int mt = 0; mt < 4; mt++) {
            int r = wm + mt * 16 + aRow;
            int kc = ks * 2 + aKc;
            ldm_x4(a[mt], aB + (uint32_t)(r * 128 + ((kc ^ (r & 7)) << 4)));
        }
#pragma unroll
        for (int np = 0; np < 4; np++) {
            int r = wn + np * 16 + bRow;
            int kc = ks * 2 + bKc;
            ldm_x4(b[np], bB + (uint32_t)(r * 128 + ((kc ^ (r & 7)) << 4)));
        }
#pragma unroll
        for (int mt = 0; mt < 4; mt++)
#pragma unroll
            for (int np = 0; np < 4; np++) {
                mma_f16(acc[mt][np * 2],     a[mt], b[np][0], b[np][1]);
                mma_f16(acc[mt][np * 2 + 1], a[mt], b[np][2], b[np][3]);
            }
    }
}

// ---------------- GEMM: C[M,N] = A[M,K] @ BT[N,K]^T -----------------------
// block tile 128x256, 3-stage cp.async pipeline, stage = A 16KB + B 32KB
#define GEMM_SMEM 147456
#define STAGE_B   49152
template <bool HALF_OUT>
__global__ void __launch_bounds__(256) gemm_h_kernel(const __half* __restrict__ A,
                                                     const __half* __restrict__ BT,
                                                     void* __restrict__ Cv,
                                                     int K, int N) {
    extern __shared__ char smem[];
    uint32_t sb = smem_u32(smem);
    int tid = threadIdx.x, lane = tid & 31, wid = tid >> 5;
    int wm = (wid & 1) * 64, wn = (wid >> 1) * 64;
    float acc[4][8][4];
#pragma unroll
    for (int mt = 0; mt < 4; mt++)
#pragma unroll
        for (int nt = 0; nt < 8; nt++)
#pragma unroll
            for (int c = 0; c < 4; c++) acc[mt][nt][c] = 0.f;

    const __half* Ab = A + (size_t)(blockIdx.y * 128) * K;
    const __half* Bb = BT + (size_t)(blockIdx.x * 256) * K;
    const __half* Bb2 = Bb + (size_t)128 * K;
    int nch = K / 64;
    // prologue: stages 0 and 1
    fill_tile(sb, Ab, K, tid);
    fill_tile(sb + 16384, Bb, K, tid);
    fill_tile(sb + 32768, Bb2, K, tid);
    CP_COMMIT();
    fill_tile(sb + STAGE_B, Ab + 64, K, tid);
    fill_tile(sb + STAGE_B + 16384, Bb + 64, K, tid);
    fill_tile(sb + STAGE_B + 32768, Bb2 + 64, K, tid);
    CP_COMMIT();

    int s = 0, nf = 2;
    for (int kc = 0; kc < nch; kc++) {
        if (kc + 1 < nch) CP_WAIT1(); else CP_WAIT0();
        __syncthreads();
        if (kc + 2 < nch) {
            uint32_t st = sb + nf * STAGE_B;
            fill_tile(st, Ab + (kc + 2) * 64, K, tid);
            fill_tile(st + 16384, Bb + (kc + 2) * 64, K, tid);
            fill_tile(st + 32768, Bb2 + (kc + 2) * 64, K, tid);
            CP_COMMIT();
            nf = (nf == 2) ? 0 : nf + 1;
        }
        compute_tile_w64(sb + s * STAGE_B, sb + s * STAGE_B + 16384, acc, lane, wm, wn);
        s = (s == 2) ? 0 : s + 1;
    }
    int row0 = blockIdx.y * 128 + wm + (lane >> 2);
    int col0 = blockIdx.x * 256 + wn + 2 * (lane & 3);
    if (HALF_OUT) {
        __half* C = (__half*)Cv;
#pragma unroll
        for (int mt = 0; mt < 4; mt++)
#pragma unroll
            for (int nt = 0; nt < 8; nt++) {
                __half* p = C + (size_t)(row0 + mt * 16) * N + col0 + nt * 8;
                *(__half2*)p = __floats2half2_rn(acc[mt][nt][0], acc[mt][nt][1]);
                *(__half2*)(p + 8 * (size_t)N) = __floats2half2_rn(acc[mt][nt][2], acc[mt][nt][3]);
            }
    } else {
        float* C = (float*)Cv;
#pragma unroll
        for (int mt = 0; mt < 4; mt++)
#pragma unroll
            for (int nt = 0; nt < 8; nt++) {
                float* p = C + (size_t)(row0 + mt * 16) * N + col0 + nt * 8;
                *(float2*)p = make_float2(acc[mt][nt][0], acc[mt][nt][1]);
                *(float2*)(p + 8 * (size_t)N) = make_float2(acc[mt][nt][2], acc[mt][nt][3]);
            }
    }
}

// ---------------- FA2-style row tile: 16 rows x 128 cols per warp ---------
__device__ __forceinline__ void compute_rowtile(uint32_t aB, uint32_t bB,
                                                float acc[16][4], int lane, int wm) {
    int g = lane >> 3, l7 = lane & 7;
    int aRow = wm + ((g & 1) << 3) + l7;
    int aKc = g >> 1;
    int bRowBase = ((g >> 1) << 3) + l7;
    int bKc = g & 1;
#pragma unroll
    for (int ks = 0; ks < 4; ks++) {
        uint32_t a[4];
        int kca = ks * 2 + aKc;
        ldm_x4(a, aB + (uint32_t)(aRow * 128 + ((kca ^ (aRow & 7)) << 4)));
        uint32_t b[8][4];
        int kcb = ks * 2 + bKc;
#pragma unroll
        for (int np = 0; np < 8; np++) {
            int r = np * 16 + bRowBase;
            ldm_x4(b[np], bB + (uint32_t)(r * 128 + ((kcb ^ (r & 7)) << 4)));
        }
#pragma unroll
        for (int np = 0; np < 8; np++) {
            mma_f16(acc[np * 2],     a, b[np][0], b[np][1]);
            mma_f16(acc[np * 2 + 1], a, b[np][2], b[np][3]);
        }
    }
}

// PV with A fragment in registers (one k16 group over keys)
__device__ __forceinline__ void compute_pv_group(const uint32_t a[4], uint32_t bB, int kgrp,
                                                 float acc[16][4], int lane) {
    int g = lane >> 3, l7 = lane & 7;
    int bRowBase = ((g >> 1) << 3) + l7;
    int bKc = g & 1;
    int kcb = kgrp * 2 + bKc;
    uint32_t b[8][4];
#pragma unroll
    for (int np = 0; np < 8; np++) {
        int r = np * 16 + bRowBase;
        ldm_x4(b[np], bB + (uint32_t)(r * 128 + ((kcb ^ (r & 7)) << 4)));
    }
#pragma unroll
    for (int np = 0; np < 8; np++) {
        mma_f16(acc[np * 2],     a, b[np][0], b[np][1]);
        mma_f16(acc[np * 2 + 1], a, b[np][2], b[np][3]);
    }
}

// ---------------- fused flash attention (FA2 warp layout) ------------------
// smem: Q 2x16K | set0{K 2x16K, V 2x16K} | set1{K, V}  = 163840 B
#define FL_SMEM 163840
__global__ void __launch_bounds__(256, 1) flash_kernel(const __half* __restrict__ Q,
                                                       const __half* __restrict__ Kmat,
                                                       const __half* __restrict__ VT,
                                                       const float* __restrict__ mask,
                                                       __half* __restrict__ O) {
    int n = NBLK - 1 - blockIdx.x;           // heavy blocks first
    int h = blockIdx.y, kvh = h >> 2;
    extern __shared__ char smem[];
    uint32_t sb = smem_u32(smem);
    int tid = threadIdx.x, lane = tid & 31, wid = tid >> 5;
    int wm = wid * 16;                        // 16 rows per warp
    int q2 = 2 * (lane & 3);
    int r0 = lane >> 2;

    // valid key-block list (bit 8 flags the causal block j==3)
    int vkb[8], nv = 0;
#pragma unroll
    for (int j = 0; j < 8; j++) {
        bool v; int kb = key_block(n, j, &v);
        if (v) { vkb[nv] = kb | ((j == 3) ? 0x100 : 0); nv++; }
    }

    // prologue: Q (group), K set0 (group), V set0 (group)
    const __half* Qb = Q + (size_t)(n * 128) * QKV_N + h * HD;
    fill_tile(sb, Qb, QKV_N, tid);
    fill_tile(sb + 16384, Qb + 64, QKV_N, tid);
    CP_COMMIT();
    {
        int kb0 = vkb[0] & 0xFF;
        const __half* Kb0 = Kmat + (size_t)(kb0 * 128) * QKV_N + kvh * HD;
        fill_tile(sb + 32768, Kb0, QKV_N, tid);
        fill_tile(sb + 49152, Kb0 + 64, QKV_N, tid);
        CP_COMMIT();
        const __half* Vb0 = VT + (size_t)kvh * HD * S_LEN + kb0 * 128;
        fill_tile(sb + 65536, Vb0, S_LEN, tid);
        fill_tile(sb + 81920, Vb0 + 64, S_LEN, tid);
        CP_COMMIT();
    }

    float Oacc[16][4];
#pragma unroll
    for (int nt = 0; nt < 16; nt++)
#pragma unroll
        for (int c = 0; c < 4; c++) Oacc[nt][c] = 0.f;
    float m0 = -1e30f, m1 = -1e30f, l0 = 0.f, l1 = 0.f;

    for (int i = 0; i < nv; i++) {
        int kb = vkb[i] & 0xFF;
        bool causal = (vkb[i] & 0x100) != 0;
        bool more = (i + 1 < nv);
        uint32_t sK = sb + 32768 + (uint32_t)(i & 1) * 65536;
        uint32_t sV = sK + 32768;

        // K ready (and Q on first iter); V of this set still pending
        CP_WAIT1();
        __syncthreads();

        // ---- S = Q @ K_blk^T (16 rows x 128 keys per warp) ----
        float Sacc[16][4];
#pragma unroll
        for (int nt = 0; nt < 16; nt++)
#pragma unroll
            for (int c = 0; c < 4; c++) Sacc[nt][c] = 0.f;
        compute_rowtile(sb, sK, Sacc, lane, wm);
        compute_rowtile(sb + 16384, sK + 16384, Sacc, lane, wm);

        // prefetch next block's K and V into the other set
        if (more) {
            int kb2 = vkb[i + 1] & 0xFF;
            uint32_t dK = sb + 32768 + (uint32_t)((i + 1) & 1) * 65536;
            const __half* Kb2 = Kmat + (size_t)(kb2 * 128) * QKV_N + kvh * HD;
            fill_tile(dK, Kb2, QKV_N, tid);
            fill_tile(dK + 16384, Kb2 + 64, QKV_N, tid);
            CP_COMMIT();
            const __half* Vb2 = VT + (size_t)kvh * HD * S_LEN + kb2 * 128;
            fill_tile(dK + 32768, Vb2, S_LEN, tid);
            fill_tile(dK + 49152, Vb2 + 64, S_LEN, tid);
            CP_COMMIT();
        }

        // ---- bias: mask + causal (register-only) ----
        const float* mrow = mask + kb * 128;
        int t0 = wm + r0;
#pragma unroll
        for (int nt = 0; nt < 16; nt++) {
            int s0 = nt * 8 + q2;
            float b0 = (1.0f - mrow[s0]) * NEGV;
            float b1 = (1.0f - mrow[s0 + 1]) * NEGV;
            Sacc[nt][0] += b0; Sacc[nt][1] += b1;
            Sacc[nt][2] += b0; Sacc[nt][3] += b1;
            if (causal) {
                if (s0 > t0) Sacc[nt][0] += NEGV;
                if (s0 + 1 > t0) Sacc[nt][1] += NEGV;
                if (s0 > t0 + 8) Sacc[nt][2] += NEGV;
                if (s0 + 1 > t0 + 8) Sacc[nt][3] += NEGV;
            }
        }

        // ---- row max (quad shuffle only) ----
        float v0 = -1e30f, v1 = -1e30f;
#pragma unroll
        for (int nt = 0; nt < 16; nt++) {
            v0 = fmaxf(v0, fmaxf(Sacc[nt][0], Sacc[nt][1]));
            v1 = fmaxf(v1, fmaxf(Sacc[nt][2], Sacc[nt][3]));
        }
        v0 = fmaxf(v0, __shfl_xor_sync(0xffffffffu, v0, 1));
        v0 = fmaxf(v0, __shfl_xor_sync(0xffffffffu, v0, 2));
        v1 = fmaxf(v1, __shfl_xor_sync(0xffffffffu, v1, 1));
        v1 = fmaxf(v1, __shfl_xor_sync(0xffffffffu, v1, 2));
        float mn0 = fmaxf(m0, v0), mn1 = fmaxf(m1, v1);
        float al0 = ex2f(m0 - mn0), al1 = ex2f(m1 - mn1);

        // ---- P = exp2(S - m), O rescale, partial sums ----
        float ps0 = 0.f, ps1 = 0.f;
#pragma unroll
        for (int nt = 0; nt < 16; nt++) {
            float p0 = ex2f(Sacc[nt][0] - mn0);
            float p1 = ex2f(Sacc[nt][1] - mn0);
            float p2 = ex2f(Sacc[nt][2] - mn1);
            float p3 = ex2f(Sacc[nt][3] - mn1);
            Sacc[nt][0] = p0; Sacc[nt][1] = p1;
            Sacc[nt][2] = p2; Sacc[nt][3] = p3;
            ps0 += p0 + p1; ps1 += p2 + p3;
            Oacc[nt][0] *= al0; Oacc[nt][1] *= al0;
            Oacc[nt][2] *= al1; Oacc[nt][3] *= al1;
        }
        ps0 += __shfl_xor_sync(0xffffffffu, ps0, 1);
        ps0 += __shfl_xor_sync(0xffffffffu, ps0, 2);
        ps1 += __shfl_xor_sync(0xffffffffu, ps1, 1);
        ps1 += __shfl_xor_sync(0xffffffffu, ps1, 2);
        l0 = l0 * al0 + ps0; l1 = l1 * al1 + ps1;
        m0 = mn0; m1 = mn1;

        // ---- convert P accumulator fragments into A operand fragments ----
        uint32_t Pf[8][4];
#pragma unroll
        for (int c = 0; c < 8; c++) {
            Pf[c][0] = packh2(Sacc[2 * c][0], Sacc[2 * c][1]);
            Pf[c][1] = packh2(Sacc[2 * c][2], Sacc[2 * c][3]);
            Pf[c][2] = packh2(Sacc[2 * c + 1][0], Sacc[2 * c + 1][1]);
            Pf[c][3] = packh2(Sacc[2 * c + 1][2], Sacc[2 * c + 1][3]);
        }

        // V ready (next set's K/V remain pending if more)
        if (more) CP_WAIT2(); else CP_WAIT0();
        __syncthreads();

        // ---- O += P @ V (A from registers) ----
#pragma unroll
        for (int c = 0; c < 4; c++)
            compute_pv_group(Pf[c], sV, c, Oacc, lane);
#pragma unroll
        for (int c = 4; c < 8; c++)
            compute_pv_group(Pf[c], sV + 16384, c - 4, Oacc, lane);
        // no end barrier: next iteration's CP_WAIT1 + __syncthreads orders
        // these reads before any refill of this set
    }

    // ---- epilogue: O /= l, write half ----
    float inv0 = 1.0f / l0, inv1 = 1.0f / l1;
    int rowA = n * 128 + wm + r0;
#pragma unroll
    for (int nt = 0; nt < 16; nt++) {
        int col = h * HD + nt * 8 + q2;
        *(__half2*)(O + (size_t)rowA * (NH * HD) + col) =
            __floats2half2_rn(Oacc[nt][0] * inv0, Oacc[nt][1] * inv0);
        *(__half2*)(O + (size_t)(rowA + 8) * (NH * HD) + col) =
            __floats2half2_rn(Oacc[nt][2] * inv1, Oacc[nt][3] * inv1);
    }
}

// ---------------- transpose float src[R][C] -> half dst[C][R] --------------
__global__ void transpose_f2h_kernel(const float* __restrict__ src, __half* __restrict__ dst,
                                     int R, int C) {
    __shared__ float t[32][33];
    int bx = blockIdx.x * 32, by = blockIdx.y * 32;
    int x = bx + threadIdx.x;
#pragma unroll
    for (int i = 0; i < 32; i += 8) {
        int y = by + threadIdx.y + i;
        t[threadIdx.y + i][threadIdx.x] = src[(size_t)y * C + x];
    }
    __syncthreads();
    int x2 = by + threadIdx.x;
#pragma unroll
    for (int i = 0; i < 32; i += 8) {
        int y2 = bx + threadIdx.y + i;
        dst[(size_t)y2 * R + x2] = __float2half_rn(t[threadIdx.x][threadIdx.y + i]);
    }
}

// ---------------- transpose half src (ld=sld) -> half dst[C][R] ------------
__global__ void transpose_h2h_kernel(const __half* __restrict__ src, __half* __restrict__ dst,
                                     int R, int C, int sld) {
    __shared__ __half t[32][33];
    int bx = blockIdx.x * 32, by = blockIdx.y * 32;
    int x = bx + threadIdx.x;
#pragma unroll
    for (int i = 0; i < 32; i += 8) {
        int y = by + threadIdx.y + i;
        t[threadIdx.y + i][threadIdx.x] = src[(size_t)y * sld + x];
    }
    __syncthreads();
    int x2 = by + threadIdx.x;
#pragma unroll
    for (int i = 0; i < 32; i += 8) {
        int y2 = bx + threadIdx.y + i;
        dst[(size_t)y2 * R + x2] = t[threadIdx.x][threadIdx.y + i];
    }
}

// ---------------- float -> half convert ------------------------------------
__global__ void f2h_kernel(const float* __restrict__ src, __half* __restrict__ dst, int n4) {
    int i = blockIdx.x * blockDim.x + threadIdx.x;
    if (i >= n4) return;
    float4 v = ((const float4*)src)[i];
    __half2 a = __floats2half2_rn(v.x, v.y);
    __half2 b = __floats2half2_rn(v.z, v.w);
    ((uint2*)dst)[i] = make_uint2(*(uint32_t*)&a, *(uint32_t*)&b);
}

// ---------------- RoPE on Q+K slices (20 heads), f32 math ------------------
__global__ void rope_h_kernel(__half* __restrict__ X,
                              const float* __restrict__ cosb,
                              const float* __restrict__ sinb) {
    int idx = blockIdx.x * blockDim.x + threadIdx.x;
    const int NHT = NH + NKV;  // 20
    int total = S_LEN * NHT * 64;
    if (idx >= total) return;
    int d = idx & 63;
    int hh = (idx >> 6) % NHT;
    int s = idx / (64 * NHT);
    float scale = (hh < NH) ? QSCALE : 1.0f;
    float c1 = cosb[s * HD + d],      s1 = sinb[s * HD + d];
    float c2 = cosb[s * HD + d + 64], s2 = sinb[s * HD + d + 64];
    __half* p = X + (size_t)s * QKV_N + hh * HD + d;
    float x1 = __half2float(p[0]), x2 = __half2float(p[64]);
    p[0]  = __float2half_rn((x1 * c1 - x2 * s1) * scale);
    p[64] = __float2half_rn((x2 * c2 + x1 * s2) * scale);
}

// ---------------- launch --------------------------------------------------
extern "C" void kernel_launch(void* const* d_in, const int* in_sizes, int n_in,
                              void* d_out, int out_size) {
    const float* H    = (const float*)d_in[0];
    const float* mask = (const float*)d_in[1];
    const float* cosb = (const float*)d_in[2];
    const float* sinb = (const float*)d_in[3];
    const float* Wq   = (const float*)d_in[4];
    const float* Wk   = (const float*)d_in[5];
    const float* Wv   = (const float*)d_in[6];
    const float* Wo   = (const float*)d_in[7];
    float* out = (float*)d_out;

    __half *Hh, *QKV, *VTh, *Oh, *WqkvT, *WoT;
    cudaGetSymbolAddress((void**)&Hh, g_Hh);
    cudaGetSymbolAddress((void**)&QKV, g_QKVh);
    cudaGetSymbolAddress((void**)&VTh, g_VTh);
    cudaGetSymbolAddress((void**)&Oh, g_Oh);
    cudaGetSymbolAddress((void**)&WqkvT, g_WqkvT);
    cudaGetSymbolAddress((void**)&WoT, g_WoTh);

    cudaFuncSetAttribute(gemm_h_kernel<true>,  cudaFuncAttributeMaxDynamicSharedMemorySize, GEMM_SMEM);
    cudaFuncSetAttribute(gemm_h_kernel<false>, cudaFuncAttributeMaxDynamicSharedMemorySize, GEMM_SMEM);
    cudaFuncSetAttribute(flash_kernel,         cudaFuncAttributeMaxDynamicSharedMemorySize, FL_SMEM);

    dim3 tb(32, 8);
    f2h_kernel<<<(S_LEN * HID / 4 + 255) / 256, 256>>>(H, Hh, S_LEN * HID / 4);
    transpose_f2h_kernel<<<dim3(64, 64), tb>>>(Wq, WqkvT, HID, NH * HD);
    transpose_f2h_kernel<<<dim3(16, 64), tb>>>(Wk, WqkvT + (size_t)(NH * HD) * HID, HID, NKV * HD);
    transpose_f2h_kernel<<<dim3(16, 64), tb>>>(Wv, WqkvT + (size_t)(NH * HD + NKV * HD) * HID, HID, NKV * HD);
    transpose_f2h_kernel<<<dim3(64, 64), tb>>>(Wo, WoT, NH * HD, HID);

    // fused QKV projection: [S,2048] @ [2048,3072], 128x256 tiles
    gemm_h_kernel<true><<<dim3(QKV_N / 256, 32), 256, GEMM_SMEM>>>(Hh, WqkvT, QKV, HID, QKV_N);

    // RoPE on Q (log2e-folded scale) + K, single launch
    rope_h_kernel<<<(S_LEN * (NH + NKV) * 64 + 255) / 256, 256>>>(QKV, cosb, sinb);

    // V^T from V slice
    transpose_h2h_kernel<<<dim3(16, 128), tb>>>(QKV + NH * HD + NKV * HD, VTh, S_LEN, NKV * HD, QKV_N);

    flash_kernel<<<dim3(NBLK, NH), 256, FL_SMEM>>>(QKV, QKV + NH * HD, VTh, mask, Oh);

    gemm_h_kernel<false><<<dim3(HID / 256, 32), 256, GEMM_SMEM>>>(Oh, WoT, out, NH * HD, HID);
}

// round 17
// speedup vs baseline: 1.0800x; 1.0800x over previous
#include <cuda_runtime.h>
#include <cuda_fp16.h>
#include <cstdint>

#define S_LEN 4096
#define HID   2048
#define NH    16
#define NKV   4
#define HD    128
#define NBLK  32
#define QKV_N 3072          // NH*HD + 2*NKV*HD
#define NEGV  -1000000000.0f
// HD^-0.5 * log2(e): softmax runs in the exp2 domain
#define QSCALE (0.08838834764831845f * 1.4426950408889634f)

// ---------------- scratch (half operands) ----------------
__device__ __half g_Hh[S_LEN * HID];
__device__ __half g_QKVh[(size_t)S_LEN * QKV_N];          // Q | K | V column slices
__device__ __half g_VTh[(size_t)NKV * HD * S_LEN];
__device__ __half g_Oh[S_LEN * NH * HD];
__device__ __half g_WqkvT[(size_t)QKV_N * HID];           // [WqT;WkT;WvT] rows
__device__ __half g_WoTh[(size_t)NH * HD * HID];

// ---------------- helpers ----------------
__device__ __forceinline__ uint32_t smem_u32(const void* p) {
    uint32_t a;
    asm("{ .reg .u64 t; cvta.to.shared.u64 t, %1; cvt.u32.u64 %0, t; }" : "=r"(a) : "l"(p));
    return a;
}
__device__ __forceinline__ float ex2f(float x) {
    float y;
    asm("ex2.approx.ftz.f32 %0, %1;" : "=f"(y) : "f"(x));
    return y;
}
__device__ __forceinline__ uint32_t packh2(float x, float y) {
    __half2 h = __floats2half2_rn(x, y);
    return *(uint32_t*)&h;
}
__device__ __forceinline__ void cp16(uint32_t dst, const void* src) {
    asm volatile("cp.async.cg.shared.global [%0], [%1], 16;" :: "r"(dst), "l"(src));
}
#define CP_COMMIT() asm volatile("cp.async.commit_group;" ::: "memory")
#define CP_WAIT0()  asm volatile("cp.async.wait_group 0;" ::: "memory")
#define CP_WAIT1()  asm volatile("cp.async.wait_group 1;" ::: "memory")
#define CP_WAIT2()  asm volatile("cp.async.wait_group 2;" ::: "memory")

__device__ __forceinline__ void mma_f16(float c[4], const uint32_t a[4],
                                        uint32_t b0, uint32_t b1) {
    asm volatile(
        "mma.sync.aligned.m16n8k16.row.col.f32.f16.f16.f32 "
        "{%0,%1,%2,%3}, {%4,%5,%6,%7}, {%8,%9}, {%0,%1,%2,%3};"
        : "+f"(c[0]), "+f"(c[1]), "+f"(c[2]), "+f"(c[3])
        : "r"(a[0]), "r"(a[1]), "r"(a[2]), "r"(a[3]), "r"(b0), "r"(b1));
}
__device__ __forceinline__ void ldm_x4(uint32_t r[4], uint32_t addr) {
    asm volatile("ldmatrix.sync.aligned.m8n8.x4.shared.b16 {%0,%1,%2,%3}, [%4];"
                 : "=r"(r[0]), "=r"(r[1]), "=r"(r[2]), "=r"(r[3]) : "r"(addr));
}

// ---------------- key-block schedule ----------------
__device__ __forceinline__ int key_block(int n, int j, bool* valid) {
    if (j < 4) {
        int kb = n - 3 + j;
        *valid = (kb >= 0);
        return kb < 0 ? 0 : kb;
    }
    int jj = j - 4;
    if (jj == 0) { *valid = true; return 0; }
    int off = (4 - jj) * 8;
    int kb = n - off; if (kb < 0) kb = 0;
    int kprev;
    if (jj == 1) kprev = 0;
    else { int po = (5 - jj) * 8; kprev = n - po; if (kprev < 0) kprev = 0; }
    *valid = (kb != kprev);
    return kb;
}

// ---------------- smem tile: 128 rows x 64 halfs (128B), XOR swizzled -----
__device__ __forceinline__ void fill_tile(uint32_t st, const __half* src, int stride, int tid) {
#pragma unroll
    for (int i = 0; i < 4; i++) {
        int idx = tid + i * 256;
        int r = idx >> 3, c8 = idx & 7;
        cp16(st + (uint32_t)((r << 3) + (c8 ^ (r & 7))) * 16,
             src + (size_t)r * stride + c8 * 8);
    }
}

// ---------------- fp16 128x128x64 compute, 64x32 warp tiles (GEMM) --------
__device__ __forceinline__ void compute_tile(uint32_t aB, uint32_t bB,
                                             float acc[4][4][4],
                                             int lane, int wm, int wn) {
    int g = lane >> 3, l7 = lane & 7;
    int aRow = ((g & 1) << 3) + l7, aKc = g >> 1;
    int bRow = ((g >> 1) << 3) + l7, bKc = g & 1;
#pragma unroll
    for (int ks = 0; ks < 4; ks++) {
        uint32_t a[4][4], b[2][4];
#pragma unroll
        for (int mt = 0; mt < 4; mt++) {
            int r = wm + mt * 16 + aRow;
            int kc = ks * 2 + aKc;
            ldm_x4(a[mt], aB + (uint32_t)(r * 128 + ((kc ^ (r & 7)) << 4)));
        }
#pragma unroll
        for (int np = 0; np < 2; np++) {
            int r = wn + np * 16 + bRow;
            int kc = ks * 2 + bKc;
            ldm_x4(b[np], bB + (uint32_t)(r * 128 + ((kc ^ (r & 7)) << 4)));
        }
#pragma unroll
        for (int mt = 0; mt < 4; mt++)
#pragma unroll
            for (int np = 0; np < 2; np++) {
                mma_f16(acc[mt][np * 2],     a[mt], b[np][0], b[np][1]);
                mma_f16(acc[mt][np * 2 + 1], a[mt], b[np][2], b[np][3]);
            }
    }
}

// ---------------- GEMM: C[M,N] = A[M,K] @ BT[N,K]^T, 3-stage pipeline -----
// occ 2: 2 x 98304B smem = 196KB <= 228KB carveout, regs capped at 128.
#define GEMM_SMEM 98304
template <bool HALF_OUT>
__global__ void __launch_bounds__(256, 2) gemm_h_kernel(const __half* __restrict__ A,
                                                        const __half* __restrict__ BT,
                                                        void* __restrict__ Cv,
                                                        int K, int N) {
    extern __shared__ char smem[];
    uint32_t sb = smem_u32(smem);
    int tid = threadIdx.x, lane = tid & 31, wid = tid >> 5;
    int wm = (wid & 1) * 64, wn = (wid >> 1) * 32;
    float acc[4][4][4];
#pragma unroll
    for (int mt = 0; mt < 4; mt++)
#pragma unroll
        for (int nt = 0; nt < 4; nt++)
#pragma unroll
            for (int c = 0; c < 4; c++) acc[mt][nt][c] = 0.f;

    const __half* Ab = A + (size_t)(blockIdx.y * 128) * K;
    const __half* Bb = BT + (size_t)(blockIdx.x * 128) * K;
    int nch = K / 64;
    fill_tile(sb, Ab, K, tid);
    fill_tile(sb + 16384, Bb, K, tid);
    CP_COMMIT();
    fill_tile(sb + 32768, Ab + 64, K, tid);
    fill_tile(sb + 32768 + 16384, Bb + 64, K, tid);
    CP_COMMIT();

    int s = 0, nf = 2;
    for (int kc = 0; kc < nch; kc++) {
        if (kc + 1 < nch) CP_WAIT1(); else CP_WAIT0();
        __syncthreads();
        if (kc + 2 < nch) {
            uint32_t st = sb + nf * 32768;
            fill_tile(st, Ab + (kc + 2) * 64, K, tid);
            fill_tile(st + 16384, Bb + (kc + 2) * 64, K, tid);
            CP_COMMIT();
            nf = (nf == 2) ? 0 : nf + 1;
        }
        compute_tile(sb + s * 32768, sb + s * 32768 + 16384, acc, lane, wm, wn);
        s = (s == 2) ? 0 : s + 1;
    }
    int row0 = blockIdx.y * 128 + wm + (lane >> 2);
    int col0 = blockIdx.x * 128 + wn + 2 * (lane & 3);
    if (HALF_OUT) {
        __half* C = (__half*)Cv;
#pragma unroll
        for (int mt = 0; mt < 4; mt++)
#pragma unroll
            for (int nt = 0; nt < 4; nt++) {
                __half* p = C + (size_t)(row0 + mt * 16) * N + col0 + nt * 8;
                *(__half2*)p = __floats2half2_rn(acc[mt][nt][0], acc[mt][nt][1]);
                *(__half2*)(p + 8 * (size_t)N) = __floats2half2_rn(acc[mt][nt][2], acc[mt][nt][3]);
            }
    } else {
        float* C = (float*)Cv;
#pragma unroll
        for (int mt = 0; mt < 4; mt++)
#pragma unroll
            for (int nt = 0; nt < 4; nt++) {
                float* p = C + (size_t)(row0 + mt * 16) * N + col0 + nt * 8;
                *(float2*)p = make_float2(acc[mt][nt][0], acc[mt][nt][1]);
                *(float2*)(p + 8 * (size_t)N) = make_float2(acc[mt][nt][2], acc[mt][nt][3]);
            }
    }
}

// ---------------- FA2-style row tile: 16 rows x 128 cols per warp ---------
__device__ __forceinline__ void compute_rowtile(uint32_t aB, uint32_t bB,
                                                float acc[16][4], int lane, int wm) {
    int g = lane >> 3, l7 = lane & 7;
    int aRow = wm + ((g & 1) << 3) + l7;
    int aKc = g >> 1;
    int bRowBase = ((g >> 1) << 3) + l7;
    int bKc = g & 1;
#pragma unroll
    for (int ks = 0; ks < 4; ks++) {
        uint32_t a[4];
        int kca = ks * 2 + aKc;
        ldm_x4(a, aB + (uint32_t)(aRow * 128 + ((kca ^ (aRow & 7)) << 4)));
        uint32_t b[8][4];
        int kcb = ks * 2 + bKc;
#pragma unroll
        for (int np = 0; np < 8; np++) {
            int r = np * 16 + bRowBase;
            ldm_x4(b[np], bB + (uint32_t)(r * 128 + ((kcb ^ (r & 7)) << 4)));
        }
#pragma unroll
        for (int np = 0; np < 8; np++) {
            mma_f16(acc[np * 2],     a, b[np][0], b[np][1]);
            mma_f16(acc[np * 2 + 1], a, b[np][2], b[np][3]);
        }
    }
}

// PV with A fragment in registers (one k16 group over keys)
__device__ __forceinline__ void compute_pv_group(const uint32_t a[4], uint32_t bB, int kgrp,
                                                 float acc[16][4], int lane) {
    int g = lane >> 3, l7 = lane & 7;
    int bRowBase = ((g >> 1) << 3) + l7;
    int bKc = g & 1;
    int kcb = kgrp * 2 + bKc;
    uint32_t b[8][4];
#pragma unroll
    for (int np = 0; np < 8; np++) {
        int r = np * 16 + bRowBase;
        ldm_x4(b[np], bB + (uint32_t)(r * 128 + ((kcb ^ (r & 7)) << 4)));
    }
#pragma unroll
    for (int np = 0; np < 8; np++) {
        mma_f16(acc[np * 2],     a, b[np][0], b[np][1]);
        mma_f16(acc[np * 2 + 1], a, b[np][2], b[np][3]);
    }
}

// ---------------- fused flash attention (FA2 warp layout) ------------------
// smem: Q 2x16K | set0{K 2x16K, V 2x16K} | set1{K, V}  = 163840 B
#define FL_SMEM 163840
__global__ void __launch_bounds__(256, 1) flash_kernel(const __half* __restrict__ Q,
                                                       const __half* __restrict__ Kmat,
                                                       const __half* __restrict__ VT,
                                                       const float* __restrict__ mask,
                                                       __half* __restrict__ O) {
    int n = NBLK - 1 - blockIdx.x;           // heavy blocks first
    int h = blockIdx.y, kvh = h >> 2;
    extern __shared__ char smem[];
    uint32_t sb = smem_u32(smem);
    int tid = threadIdx.x, lane = tid & 31, wid = tid >> 5;
    int wm = wid * 16;                        // 16 rows per warp
    int q2 = 2 * (lane & 3);
    int r0 = lane >> 2;

    // valid key-block list (bit 8 flags the causal block j==3)
    int vkb[8], nv = 0;
#pragma unroll
    for (int j = 0; j < 8; j++) {
        bool v; int kb = key_block(n, j, &v);
        if (v) { vkb[nv] = kb | ((j == 3) ? 0x100 : 0); nv++; }
    }

    // prologue: Q (group), K set0 (group), V set0 (group)
    const __half* Qb = Q + (size_t)(n * 128) * QKV_N + h * HD;
    fill_tile(sb, Qb, QKV_N, tid);
    fill_tile(sb + 16384, Qb + 64, QKV_N, tid);
    CP_COMMIT();
    {
        int kb0 = vkb[0] & 0xFF;
        const __half* Kb0 = Kmat + (size_t)(kb0 * 128) * QKV_N + kvh * HD;
        fill_tile(sb + 32768, Kb0, QKV_N, tid);
        fill_tile(sb + 49152, Kb0 + 64, QKV_N, tid);
        CP_COMMIT();
        const __half* Vb0 = VT + (size_t)kvh * HD * S_LEN + kb0 * 128;
        fill_tile(sb + 65536, Vb0, S_LEN, tid);
        fill_tile(sb + 81920, Vb0 + 64, S_LEN, tid);
        CP_COMMIT();
    }

    float Oacc[16][4];
#pragma unroll
    for (int nt = 0; nt < 16; nt++)
#pragma unroll
        for (int c = 0; c < 4; c++) Oacc[nt][c] = 0.f;
    float m0 = -1e30f, m1 = -1e30f, l0 = 0.f, l1 = 0.f;

    for (int i = 0; i < nv; i++) {
        int kb = vkb[i] & 0xFF;
        bool causal = (vkb[i] & 0x100) != 0;
        bool more = (i + 1 < nv);
        uint32_t sK = sb + 32768 + (uint32_t)(i & 1) * 65536;
        uint32_t sV = sK + 32768;

        // K ready (and Q on first iter); V of this set still pending
        CP_WAIT1();
        __syncthreads();

        // ---- S = Q @ K_blk^T (16 rows x 128 keys per warp) ----
        float Sacc[16][4];
#pragma unroll
        for (int nt = 0; nt < 16; nt++)
#pragma unroll
            for (int c = 0; c < 4; c++) Sacc[nt][c] = 0.f;
        compute_rowtile(sb, sK, Sacc, lane, wm);
        compute_rowtile(sb + 16384, sK + 16384, Sacc, lane, wm);

        // prefetch next block's K and V into the other set
        if (more) {
            int kb2 = vkb[i + 1] & 0xFF;
            uint32_t dK = sb + 32768 + (uint32_t)((i + 1) & 1) * 65536;
            const __half* Kb2 = Kmat + (size_t)(kb2 * 128) * QKV_N + kvh * HD;
            fill_tile(dK, Kb2, QKV_N, tid);
            fill_tile(dK + 16384, Kb2 + 64, QKV_N, tid);
            CP_COMMIT();
            const __half* Vb2 = VT + (size_t)kvh * HD * S_LEN + kb2 * 128;
            fill_tile(dK + 32768, Vb2, S_LEN, tid);
            fill_tile(dK + 49152, Vb2 + 64, S_LEN, tid);
            CP_COMMIT();
        }

        // ---- bias: mask + causal (register-only) ----
        const float* mrow = mask + kb * 128;
        int t0 = wm + r0;
#pragma unroll
        for (int nt = 0; nt < 16; nt++) {
            int s0 = nt * 8 + q2;
            float b0 = (1.0f - mrow[s0]) * NEGV;
            float b1 = (1.0f - mrow[s0 + 1]) * NEGV;
            Sacc[nt][0] += b0; Sacc[nt][1] += b1;
            Sacc[nt][2] += b0; Sacc[nt][3] += b1;
            if (causal) {
                if (s0 > t0) Sacc[nt][0] += NEGV;
                if (s0 + 1 > t0) Sacc[nt][1] += NEGV;
                if (s0 > t0 + 8) Sacc[nt][2] += NEGV;
                if (s0 + 1 > t0 + 8) Sacc[nt][3] += NEGV;
            }
        }

        // ---- row max (quad shuffle only) ----
        float v0 = -1e30f, v1 = -1e30f;
#pragma unroll
        for (int nt = 0; nt < 16; nt++) {
            v0 = fmaxf(v0, fmaxf(Sacc[nt][0], Sacc[nt][1]));
            v1 = fmaxf(v1, fmaxf(Sacc[nt][2], Sacc[nt][3]));
        }
        v0 = fmaxf(v0, __shfl_xor_sync(0xffffffffu, v0, 1));
        v0 = fmaxf(v0, __shfl_xor_sync(0xffffffffu, v0, 2));
        v1 = fmaxf(v1, __shfl_xor_sync(0xffffffffu, v1, 1));
        v1 = fmaxf(v1, __shfl_xor_sync(0xffffffffu, v1, 2));
        float mn0 = fmaxf(m0, v0), mn1 = fmaxf(m1, v1);
        float al0 = ex2f(m0 - mn0), al1 = ex2f(m1 - mn1);

        // ---- P = exp2(S - m), O rescale, partial sums ----
        float ps0 = 0.f, ps1 = 0.f;
#pragma unroll
        for (int nt = 0; nt < 16; nt++) {
            float p0 = ex2f(Sacc[nt][0] - mn0);
            float p1 = ex2f(Sacc[nt][1] - mn0);
            float p2 = ex2f(Sacc[nt][2] - mn1);
            float p3 = ex2f(Sacc[nt][3] - mn1);
            Sacc[nt][0] = p0; Sacc[nt][1] = p1;
            Sacc[nt][2] = p2; Sacc[nt][3] = p3;
            ps0 += p0 + p1; ps1 += p2 + p3;
            Oacc[nt][0] *= al0; Oacc[nt][1] *= al0;
            Oacc[nt][2] *= al1; Oacc[nt][3] *= al1;
        }
        ps0 += __shfl_xor_sync(0xffffffffu, ps0, 1);
        ps0 += __shfl_xor_sync(0xffffffffu, ps0, 2);
        ps1 += __shfl_xor_sync(0xffffffffu, ps1, 1);
        ps1 += __shfl_xor_sync(0xffffffffu, ps1, 2);
        l0 = l0 * al0 + ps0; l1 = l1 * al1 + ps1;
        m0 = mn0; m1 = mn1;

        // ---- convert P accumulator fragments into A operand fragments ----
        uint32_t Pf[8][4];
#pragma unroll
        for (int c = 0; c < 8; c++) {
            Pf[c][0] = packh2(Sacc[2 * c][0], Sacc[2 * c][1]);
            Pf[c][1] = packh2(Sacc[2 * c][2], Sacc[2 * c][3]);
            Pf[c][2] = packh2(Sacc[2 * c + 1][0], Sacc[2 * c + 1][1]);
            Pf[c][3] = packh2(Sacc[2 * c + 1][2], Sacc[2 * c + 1][3]);
        }

        // V ready (next set's K/V remain pending if more)
        if (more) CP_WAIT2(); else CP_WAIT0();
        __syncthreads();

        // ---- O += P @ V (A from registers) ----
#pragma unroll
        for (int c = 0; c < 4; c++)
            compute_pv_group(Pf[c], sV, c, Oacc, lane);
#pragma unroll
        for (int c = 4; c < 8; c++)
            compute_pv_group(Pf[c], sV + 16384, c - 4, Oacc, lane);
        // no end barrier: next iteration's CP_WAIT1 + __syncthreads orders
        // these reads before any refill of this set
    }

    // ---- epilogue: O /= l, write half ----
    float inv0 = 1.0f / l0, inv1 = 1.0f / l1;
    int rowA = n * 128 + wm + r0;
#pragma unroll
    for (int nt = 0; nt < 16; nt++) {
        int col = h * HD + nt * 8 + q2;
        *(__half2*)(O + (size_t)rowA * (NH * HD) + col) =
            __floats2half2_rn(Oacc[nt][0] * inv0, Oacc[nt][1] * inv0);
        *(__half2*)(O + (size_t)(rowA + 8) * (NH * HD) + col) =
            __floats2half2_rn(Oacc[nt][2] * inv1, Oacc[nt][3] * inv1);
    }
}

// ---------------- fused prep: f2h(H) + 4 weight transposes -----------------
// block ranges: [0,8192) f2h | [8192,12288) Wq | [12288,13312) Wk
//               [13312,14336) Wv | [14336,18432) Wo
__global__ void __launch_bounds__(256) prep_kernel(const float* __restrict__ H,
                                                   __half* __restrict__ Hh,
                                                   const float* __restrict__ Wq,
                                                   const float* __restrict__ Wk,
                                                   const float* __restrict__ Wv,
                                                   const float* __restrict__ Wo,
                                                   __half* __restrict__ WqkvT,
                                                   __half* __restrict__ WoT) {
    __shared__ float t[32][33];
    int b = blockIdx.x, tid = threadIdx.x;
    if (b < 8192) {
        int i = b * 256 + tid;
        float4 v = ((const float4*)H)[i];
        __half2 a = __floats2half2_rn(v.x, v.y);
        __half2 c = __floats2half2_rn(v.z, v.w);
        ((uint2*)Hh)[i] = make_uint2(*(uint32_t*)&a, *(uint32_t*)&c);
        return;
    }
    b -= 8192;
    const float* src; __half* dst; int R, C, gx;
    if (b < 4096)      { src = Wq; dst = WqkvT;                                   R = HID;     C = NH * HD;  gx = 64; }
    else if (b < 5120) { b -= 4096; src = Wk; dst = WqkvT + (size_t)(NH * HD) * HID;            R = HID;     C = NKV * HD; gx = 16; }
    else if (b < 6144) { b -= 5120; src = Wv; dst = WqkvT + (size_t)(NH * HD + NKV * HD) * HID; R = HID;     C = NKV * HD; gx = 16; }
    else               { b -= 6144; src = Wo; dst = WoT;                                        R = NH * HD; C = HID;      gx = 64; }
    int bx = (b % gx) * 32, by = (b / gx) * 32;
    int tx = tid & 31, ty = tid >> 5;
    int x = bx + tx;
#pragma unroll
    for (int i = 0; i < 32; i += 8) {
        int y = by + ty + i;
        t[ty + i][tx] = src[(size_t)y * C + x];
    }
    __syncthreads();
    int x2 = by + tx;
#pragma unroll
    for (int i = 0; i < 32; i += 8) {
        int y2 = bx + ty + i;
        dst[(size_t)y2 * R + x2] = __float2half_rn(t[tx][ty + i]);
    }
}

// ---------------- fused mid: RoPE(Q+K) + V transpose -----------------------
// block ranges: [0,20480) rope | [20480,22528) h2h transpose of V slice
__global__ void __launch_bounds__(256) mid_kernel(__half* __restrict__ QKV,
                                                  const float* __restrict__ cosb,
                                                  const float* __restrict__ sinb,
                                                  __half* __restrict__ VTd) {
    __shared__ __half th[32][33];
    int b = blockIdx.x, tid = threadIdx.x;
    if (b < 20480) {
        const int NHT = NH + NKV;  // 20
        int idx = b * 256 + tid;
        int d = idx & 63;
        int hh = (idx >> 6) % NHT;
        int s = idx / (64 * NHT);
        float scale = (hh < NH) ? QSCALE : 1.0f;
        float c1 = cosb[s * HD + d],      s1 = sinb[s * HD + d];
        float c2 = cosb[s * HD + d + 64], s2 = sinb[s * HD + d + 64];
        __half* p = QKV + (size_t)s * QKV_N + hh * HD + d;
        float x1 = __half2float(p[0]), x2 = __half2float(p[64]);
        p[0]  = __float2half_rn((x1 * c1 - x2 * s1) * scale);
        p[64] = __float2half_rn((x2 * c2 + x1 * s2) * scale);
        return;
    }
    b -= 20480;
    // transpose V slice: src [S_LEN rows x 512 cols, ld=QKV_N] -> VT [512 x S_LEN]
    const __half* src = QKV + NH * HD + NKV * HD;
    int bx = (b & 15) * 32, by = (b >> 4) * 32;
    int tx = tid & 31, ty = tid >> 5;
    int x = bx + tx;
#pragma unroll
    for (int i = 0; i < 32; i += 8) {
        int y = by + ty + i;
        th[ty + i][tx] = src[(size_t)y * QKV_N + x];
    }
    __syncthreads();
    int x2 = by + tx;
#pragma unroll
    for (int i = 0; i < 32; i += 8) {
        int y2 = bx + ty + i;
        VTd[(size_t)y2 * S_LEN + x2] = th[tx][ty + i];
    }
}

// ---------------- launch --------------------------------------------------
extern "C" void kernel_launch(void* const* d_in, const int* in_sizes, int n_in,
                              void* d_out, int out_size) {
    const float* H    = (const float*)d_in[0];
    const float* mask = (const float*)d_in[1];
    const float* cosb = (const float*)d_in[2];
    const float* sinb = (const float*)d_in[3];
    const float* Wq   = (const float*)d_in[4];
    const float* Wk   = (const float*)d_in[5];
    const float* Wv   = (const float*)d_in[6];
    const float* Wo   = (const float*)d_in[7];
    float* out = (float*)d_out;

    __half *Hh, *QKV, *VTh, *Oh, *WqkvT, *WoT;
    cudaGetSymbolAddress((void**)&Hh, g_Hh);
    cudaGetSymbolAddress((void**)&QKV, g_QKVh);
    cudaGetSymbolAddress((void**)&VTh, g_VTh);
    cudaGetSymbolAddress((void**)&Oh, g_Oh);
    cudaGetSymbolAddress((void**)&WqkvT, g_WqkvT);
    cudaGetSymbolAddress((void**)&WoT, g_WoTh);

    cudaFuncSetAttribute(gemm_h_kernel<true>,  cudaFuncAttributeMaxDynamicSharedMemorySize, GEMM_SMEM);
    cudaFuncSetAttribute(gemm_h_kernel<false>, cudaFuncAttributeMaxDynamicSharedMemorySize, GEMM_SMEM);
    cudaFuncSetAttribute(flash_kernel,         cudaFuncAttributeMaxDynamicSharedMemorySize, FL_SMEM);

    // fused elementwise prep: f2h + all weight transposes (1 launch)
    prep_kernel<<<18432, 256>>>(H, Hh, Wq, Wk, Wv, Wo, WqkvT, WoT);

    // fused QKV projection: [S,2048] @ [2048,3072]
    gemm_h_kernel<true><<<dim3(QKV_N / 128, 32), 256, GEMM_SMEM>>>(Hh, WqkvT, QKV, HID, QKV_N);

    // fused RoPE + V^T (1 launch)
    mid_kernel<<<22528, 256>>>(QKV, cosb, sinb, VTh);

    flash_kernel<<<dim3(NBLK, NH), 256, FL_SMEM>>>(QKV, QKV + NH * HD, VTh, mask, Oh);

    gemm_h_kernel<false><<<dim3(16, 32), 256, GEMM_SMEM>>>(Oh, WoT, out, NH * HD, HID);
}